// round 1
// baseline (speedup 1.0000x reference)
#include <cuda_runtime.h>

// Problem constants (match reference_code)
#define KS   17
#define HP   256
#define WP   256
#define HI   (HP + KS - 1)   // 272
#define WI   (WP + KS - 1)   // 272
#define BC   12              // B*C = 4*3
#define P    (HP * WP)       // 65536
#define IMG_BC_STRIDE (HI * WI)  // 73984 floats per (b,c) image plane

// Tiling: each thread computes 4 consecutive x-pixels for ALL 12 (b,c) planes.
// Block = 16 threads in x (covers 64 px) * 4 rows = 64 threads, tile 64x4.
// Grid  = (256/64, 256/4) = (4, 64) = 256 blocks.

__global__ void __launch_bounds__(64, 6)
blur_kernel(const float* __restrict__ img,
            const float* __restrict__ kernels,
            const int*   __restrict__ idx_p,
            float*       __restrict__ out)
{
    const int x0 = blockIdx.x * 64 + threadIdx.x * 4;   // multiple of 4
    const int y  = blockIdx.y * 4 + threadIdx.y;
    const int p0 = y * WP + x0;                          // multiple of 4

    // Select the per-pixel kernel slice for this idx (uniform load).
    const long long kidx = (long long)(*idx_p);
    const float* __restrict__ kern = kernels + kidx * (long long)(KS * KS) * (long long)P;

    float acc[BC][4];
#pragma unroll
    for (int bc = 0; bc < BC; bc++)
#pragma unroll
        for (int r = 0; r < 4; r++) acc[bc][r] = 0.0f;

#pragma unroll 1
    for (int kh = 0; kh < KS; kh++) {
        // img row base for this kh; bc planes at constant byte offsets (folds into LDG imm)
        const float* __restrict__ irow = img + (long long)(y + kh) * WI + x0;

        // init sliding windows: win[bc][r] = img[bc][y+kh][x0 + r]
        float win[BC][4];
#pragma unroll
        for (int bc = 0; bc < BC; bc++) {
#pragma unroll
            for (int r = 0; r < 4; r++)
                win[bc][r] = irow[bc * IMG_BC_STRIDE + r];
        }

        // kern row base for this kh, as float4 over pixels p0..p0+3
        const float4* __restrict__ krow =
            (const float4*)(kern + (long long)kh * KS * P + p0);

#pragma unroll
        for (int kw = 0; kw < KS; kw++) {
            // weights for tap (kh,kw) at pixels p0..p0+3 (coalesced DRAM stream)
            const float4 w = krow[(long long)kw * (P / 4)];

#pragma unroll
            for (int bc = 0; bc < BC; bc++) {
                acc[bc][0] = fmaf(w.x, win[bc][0], acc[bc][0]);
                acc[bc][1] = fmaf(w.y, win[bc][1], acc[bc][1]);
                acc[bc][2] = fmaf(w.z, win[bc][2], acc[bc][2]);
                acc[bc][3] = fmaf(w.w, win[bc][3], acc[bc][3]);
            }

            // shift windows (pure register renaming after unroll) + 1 new load per bc
            if (kw < KS - 1) {
#pragma unroll
                for (int bc = 0; bc < BC; bc++) {
                    win[bc][0] = win[bc][1];
                    win[bc][1] = win[bc][2];
                    win[bc][2] = win[bc][3];
                    win[bc][3] = irow[bc * IMG_BC_STRIDE + kw + 4];
                }
            }
        }
    }

    // write out: out[bc][p0..p0+3], vectorized
#pragma unroll
    for (int bc = 0; bc < BC; bc++) {
        *(float4*)(out + (long long)bc * P + p0) =
            make_float4(acc[bc][0], acc[bc][1], acc[bc][2], acc[bc][3]);
    }
}

extern "C" void kernel_launch(void* const* d_in, const int* in_sizes, int n_in,
                              void* d_out, int out_size)
{
    const float* img     = (const float*)d_in[0];  // (4,3,272,272) f32
    const float* kernels = (const float*)d_in[1];  // (16,1,289,65536) f32
    const int*   idx     = (const int*)d_in[2];    // scalar int32
    float*       out     = (float*)d_out;          // (4,3,256,256) f32

    dim3 block(16, 4);
    dim3 grid(WP / 64, HP / 4);   // (4, 64)
    blur_kernel<<<grid, block>>>(img, kernels, idx, out);
}

// round 2
// speedup vs baseline: 1.4652x; 1.4652x over previous
#include <cuda_runtime.h>

// Problem constants (match reference_code)
#define KS   17
#define HP   256
#define WP   256
#define HI   (HP + KS - 1)   // 272
#define WI   (WP + KS - 1)   // 272
#define BC   12              // B*C = 4*3
#define P    (HP * WP)       // 65536
#define IMG_BC_STRIDE (HI * WI)  // 73984 floats per (b,c) plane

// Tiling:
//   thread: 4 consecutive x-pixels x 4 (b,c) planes
//   block : (16,2,3) = 96 threads -> tile 64x2 px, all 12 bc (z splits bc)
//   grid  : (256/64, 256/2) = (4,128) = 512 blocks
// kern float4 at a given (x,y) is read by the 3 z-groups of the SAME block ->
// one DRAM read, two L1 hits. img (3.5 MB) is fully L2-resident.

__global__ void __launch_bounds__(96, 4)
blur_kernel(const float* __restrict__ img,
            const float* __restrict__ kernels,
            const int*   __restrict__ idx_p,
            float*       __restrict__ out)
{
    const int x0  = blockIdx.x * 64 + threadIdx.x * 4;  // multiple of 4
    const int y   = blockIdx.y * 2 + threadIdx.y;
    const int bc0 = threadIdx.z * 4;                    // 0,4,8
    const int p0  = y * WP + x0;                        // multiple of 4

    const long long kidx = (long long)(*idx_p);
    const float* __restrict__ kern =
        kernels + kidx * (long long)(KS * KS) * (long long)P;

    float acc[4][4];
#pragma unroll
    for (int bc = 0; bc < 4; bc++)
#pragma unroll
        for (int r = 0; r < 4; r++) acc[bc][r] = 0.0f;

#pragma unroll 1
    for (int kh = 0; kh < KS; kh++) {
        // 20-float window per bc, loaded as 5 x LDG.128 (16B-aligned: x0%4==0,
        // WI and IMG_BC_STRIDE both divisible by 4)
        const float* __restrict__ irow =
            img + (long long)(bc0) * IMG_BC_STRIDE + (long long)(y + kh) * WI + x0;

        float win[4][20];
#pragma unroll
        for (int bc = 0; bc < 4; bc++) {
#pragma unroll
            for (int v = 0; v < 5; v++) {
                const float4 t = *(const float4*)(irow + bc * IMG_BC_STRIDE + v * 4);
                win[bc][v * 4 + 0] = t.x;
                win[bc][v * 4 + 1] = t.y;
                win[bc][v * 4 + 2] = t.z;
                win[bc][v * 4 + 3] = t.w;
            }
        }

        const float4* __restrict__ krow =
            (const float4*)(kern + (long long)kh * KS * P + p0);

#pragma unroll
        for (int kw = 0; kw < KS; kw++) {
            const float4 w = krow[(long long)kw * (P / 4)];
#pragma unroll
            for (int bc = 0; bc < 4; bc++) {
                acc[bc][0] = fmaf(w.x, win[bc][kw + 0], acc[bc][0]);
                acc[bc][1] = fmaf(w.y, win[bc][kw + 1], acc[bc][1]);
                acc[bc][2] = fmaf(w.z, win[bc][kw + 2], acc[bc][2]);
                acc[bc][3] = fmaf(w.w, win[bc][kw + 3], acc[bc][3]);
            }
        }
    }

#pragma unroll
    for (int bc = 0; bc < 4; bc++) {
        *(float4*)(out + (long long)(bc0 + bc) * P + p0) =
            make_float4(acc[bc][0], acc[bc][1], acc[bc][2], acc[bc][3]);
    }
}

extern "C" void kernel_launch(void* const* d_in, const int* in_sizes, int n_in,
                              void* d_out, int out_size)
{
    const float* img     = (const float*)d_in[0];  // (4,3,272,272) f32
    const float* kernels = (const float*)d_in[1];  // (16,1,289,65536) f32
    const int*   idx     = (const int*)d_in[2];    // scalar int32
    float*       out     = (float*)d_out;          // (4,3,256,256) f32

    dim3 block(16, 2, 3);
    dim3 grid(WP / 64, HP / 2);   // (4, 128)
    blur_kernel<<<grid, block>>>(img, kernels, idx, out);
}